// round 2
// baseline (speedup 1.0000x reference)
#include <cuda_runtime.h>

#define HW       262144      // 512*512
#define HW4      65536       // HW/4
#define NB       16          // batch
#define NPLANE   48          // B*3
#define RBLOCKS  32
#define RTHREADS 256

#define EPSC 1e-8f
#define PIC  3.141592653589793f

__device__ float g_partial[NPLANE * RBLOCKS];
__device__ float g_hue_bias[NB];

// ---------------- Stage 1: per-plane partial sums (deterministic) ----------------
__global__ void reduce_kernel(const float* __restrict__ img) {
    __shared__ float sdata[RTHREADS];
    const int plane = blockIdx.y;       // 0..47  (b*3 + c)
    const int blk   = blockIdx.x;       // 0..31
    const int tid   = threadIdx.x;

    const float4* p = reinterpret_cast<const float4*>(img)
                      + (size_t)plane * HW4 + (size_t)blk * 2048;
    float s = 0.f;
#pragma unroll
    for (int i = 0; i < 8; i++) {
        float4 v = p[tid + i * RTHREADS];
        s += (v.x + v.y) + (v.z + v.w);
    }
    sdata[tid] = s;
    __syncthreads();
    for (int off = RTHREADS / 2; off > 0; off >>= 1) {
        if (tid < off) sdata[tid] += sdata[tid + off];
        __syncthreads();
    }
    if (tid == 0) g_partial[plane * RBLOCKS + blk] = sdata[0];
}

// ---------------- Stage 2: finish mean + tiny MLP -> hue_bias[b] ----------------
__global__ void mlp_kernel(const float* __restrict__ w1, const float* __restrict__ b1,
                           const float* __restrict__ w2, const float* __restrict__ b2) {
    __shared__ float s_pool[NPLANE];
    const int tid = threadIdx.x;
    if (tid < NPLANE) {
        float s = 0.f;
        for (int i = 0; i < RBLOCKS; i++) s += g_partial[tid * RBLOCKS + i];
        s_pool[tid] = s * (1.0f / (float)HW);
    }
    __syncthreads();
    if (tid < NB) {
        const float p0 = s_pool[tid * 3 + 0];
        const float p1 = s_pool[tid * 3 + 1];
        const float p2 = s_pool[tid * 3 + 2];
        float z = b2[0];
#pragma unroll
        for (int j = 0; j < 8; j++) {
            float hj = p0 * w1[j * 3 + 0] + p1 * w1[j * 3 + 1] + p2 * w1[j * 3 + 2] + b1[j];
            z += fmaxf(hj, 0.f) * w2[j];
        }
        g_hue_bias[tid] = tanhf(z) * 0.5f;
    }
}

// jnp.mod(x, m) semantics: truncated remainder then fix sign
__device__ __forceinline__ float jmod(float x, float m) {
    float r = fmodf(x, m);
    return (r < 0.f) ? r + m : r;
}

// ---------------- Stage 3: fused per-pixel transform ----------------
__device__ __forceinline__ float3 pixel_op(float r, float g, float bch, float noi,
                                           float kd, float ng, float bg, float hb) {
    const float v  = fmaxf(r, fmaxf(g, bch));
    const float mn = fminf(r, fminf(g, bch));
    const float inv_denom = __fdividef(1.f, v - mn + EPSC);

    float hue;
    if (mn == v)       hue = 0.f;
    else if (r == v)   hue = jmod((g - bch) * inv_denom, 6.f);
    else if (g == v)   hue = 2.f + (bch - r) * inv_denom;
    else if (bch == v) hue = 4.f + (r - g) * inv_denom;
    else               hue = 0.f;
    hue *= (1.f / 6.f);

    const float sat = (v == 0.f) ? 0.f : __fdividef(v - mn, v + EPSC);

    const float h4   = jmod(hue + hb, 1.f);
    const float kmap = fminf(fmaxf(kd + ng * noi - bg * v, 0.05f), 2.f);

    const float s1 = __sinf(v * (0.5f * PIC)) + EPSC;
    const float cs = __powf(s1, kmap);       // cs2 == cs (v=clip(v,0,1) identity, same k)

    float sA, cA;
    __sincosf((2.f * PIC) * h4, &sA, &cA);

    const float csat = cs * sat;
    const float Hc = fminf(fmaxf(csat * cA, -1.f), 1.f);
    const float Vc = fminf(fmaxf(csat * sA, -1.f), 1.f);

    const float inv_cs = __fdividef(1.f, cs + EPSC);
    const float Hp = fminf(fmaxf(Hc * inv_cs, -1.f), 1.f);
    const float Vp = fminf(fmaxf(Vc * inv_cs, -1.f), 1.f);

    float h = atan2f(Vp + EPSC, Hp + EPSC) * (1.f / (2.f * PIC));
    h = jmod(h, 1.f);
    h = jmod(h - hb, 1.f);

    const float s = fminf(sqrtf(Hp * Hp + Vp * Vp + EPSC), 1.f);
    const float vv = fminf(fmaxf(v, 0.f), 1.f);

    const float h6 = h * 6.f;
    const float hif = floorf(h6);
    const float f  = h6 - hif;
    const float p  = vv * (1.f - s);
    const float q  = vv * (1.f - f * s);
    const float t  = vv * (1.f - (1.f - f) * s);

    float ro, go, bo;
    switch ((int)hif) {
        case 0: ro = vv; go = t;  bo = p;  break;
        case 1: ro = q;  go = vv; bo = p;  break;
        case 2: ro = p;  go = vv; bo = t;  break;
        case 3: ro = p;  go = q;  bo = vv; break;
        case 4: ro = t;  go = p;  bo = vv; break;
        case 5: ro = vv; go = p;  bo = q;  break;
        default: ro = 0.f; go = 0.f; bo = 0.f; break;  // hi==6 edge (mod rounding)
    }
    return make_float3(ro, go, bo);
}

__global__ void __launch_bounds__(256) main_kernel(
    const float4* __restrict__ img, const float4* __restrict__ noise,
    const float* __restrict__ density_k, const float* __restrict__ noise_gain,
    const float* __restrict__ bright_gain, float4* __restrict__ out)
{
    const unsigned gid = blockIdx.x * blockDim.x + threadIdx.x;   // 0 .. 1048575
    const unsigned b  = gid >> 16;        // /HW4
    const unsigned p  = gid & (HW4 - 1);

    const size_t ibase = (size_t)b * 3 * HW4 + p;
    const float4 r4 = img[ibase];
    const float4 g4 = img[ibase + HW4];
    const float4 b4 = img[ibase + 2 * HW4];
    const float4 n4 = noise[(size_t)b * HW4 + p];

    const float kd = density_k[0];
    const float ng = noise_gain[0];
    const float bg = bright_gain[0];
    const float hb = g_hue_bias[b];

    float4 ro4, go4, bo4;
    {
        float3 o = pixel_op(r4.x, g4.x, b4.x, n4.x, kd, ng, bg, hb);
        ro4.x = o.x; go4.x = o.y; bo4.x = o.z;
    }
    {
        float3 o = pixel_op(r4.y, g4.y, b4.y, n4.y, kd, ng, bg, hb);
        ro4.y = o.x; go4.y = o.y; bo4.y = o.z;
    }
    {
        float3 o = pixel_op(r4.z, g4.z, b4.z, n4.z, kd, ng, bg, hb);
        ro4.z = o.x; go4.z = o.y; bo4.z = o.z;
    }
    {
        float3 o = pixel_op(r4.w, g4.w, b4.w, n4.w, kd, ng, bg, hb);
        ro4.w = o.x; go4.w = o.y; bo4.w = o.z;
    }

    out[ibase]           = ro4;
    out[ibase + HW4]     = go4;
    out[ibase + 2 * HW4] = bo4;
}

extern "C" void kernel_launch(void* const* d_in, const int* in_sizes, int n_in,
                              void* d_out, int out_size) {
    const float* img   = (const float*)d_in[0];
    const float* noise = (const float*)d_in[1];
    const float* kd    = (const float*)d_in[2];
    const float* ng    = (const float*)d_in[3];
    const float* bg    = (const float*)d_in[4];
    const float* w1    = (const float*)d_in[5];
    const float* b1    = (const float*)d_in[6];
    const float* w2    = (const float*)d_in[7];
    const float* b2    = (const float*)d_in[8];
    float* out = (float*)d_out;

    dim3 rgrid(RBLOCKS, NPLANE);
    reduce_kernel<<<rgrid, RTHREADS>>>(img);
    mlp_kernel<<<1, 64>>>(w1, b1, w2, b2);
    main_kernel<<<(NB * HW4) / 256, 256>>>(
        (const float4*)img, (const float4*)noise, kd, ng, bg, (float4*)out);
}

// round 3
// speedup vs baseline: 2.0282x; 2.0282x over previous
#include <cuda_runtime.h>

#define HW       262144      // 512*512
#define HW4      65536       // HW/4
#define NB       16          // batch

#define EPSC 1e-8f
#define PIC  3.141592653589793f

// jnp.mod semantics: truncated remainder then fix sign
__device__ __forceinline__ float jmod6(float x) {
    float r = fmodf(x, 6.f);
    return (r < 0.f) ? r + 6.f : r;
}

// Fused per-pixel transform.
// Analytic identity: the reference's sincos(2*pi*h4) -> scale -> atan2 -> mod(-hue_bias)
// chain reconstructs the original hue exactly (hue_bias cancels), and
// s = clip(sqrt((sat*rho)^2 + eps)) with rho = cs/(cs+eps). The +eps perturbations
// inside atan2 only matter when sat*rho ~ 1e-4, where s ~ 1e-4 makes h irrelevant
// to the output at the 1e-4 level (<< 1e-3 gate).
__device__ __forceinline__ float3 pixel_op(float r, float g, float bch, float noi,
                                           float kd, float ng, float bg) {
    const float v  = fmaxf(r, fmaxf(g, bch));
    const float mn = fminf(r, fminf(g, bch));
    const float inv_denom = __fdividef(1.f, v - mn + EPSC);

    float hue;
    if (mn == v)       hue = 0.f;
    else if (r == v)   hue = jmod6((g - bch) * inv_denom);
    else if (g == v)   hue = 2.f + (bch - r) * inv_denom;
    else               hue = 4.f + (r - g) * inv_denom;   // b == v
    hue *= (1.f / 6.f);

    const float sat = (v == 0.f) ? 0.f : __fdividef(v - mn, v + EPSC);

    const float kmap = fminf(fmaxf(kd + ng * noi - bg * v, 0.05f), 2.f);
    const float s1 = __sinf(v * (0.5f * PIC)) + EPSC;
    const float cs = __powf(s1, kmap);
    const float rho = cs * __fdividef(1.f, cs + EPSC);    // cs/(cs+eps)

    const float sr = sat * rho;
    const float x  = fmaf(sr, sr, EPSC);
    const float s  = fminf(x * rsqrtf(x), 1.f);           // sqrt(x), clipped to 1
    const float vv = fminf(fmaxf(v, 0.f), 1.f);

    const float h6  = hue * 6.f;
    const float hif = floorf(h6);
    const float f   = h6 - hif;
    const float p   = vv * (1.f - s);
    const float q   = vv * (1.f - f * s);
    const float t   = vv * (1.f - (1.f - f) * s);

    float ro, go, bo;
    switch ((int)hif) {
        case 0: ro = vv; go = t;  bo = p;  break;
        case 1: ro = q;  go = vv; bo = p;  break;
        case 2: ro = p;  go = vv; bo = t;  break;
        case 3: ro = p;  go = q;  bo = vv; break;
        case 4: ro = t;  go = p;  bo = vv; break;
        case 5: ro = vv; go = p;  bo = q;  break;
        default: ro = 0.f; go = 0.f; bo = 0.f; break;
    }
    return make_float3(ro, go, bo);
}

__global__ void __launch_bounds__(256) main_kernel(
    const float4* __restrict__ img, const float4* __restrict__ noise,
    const float* __restrict__ density_k, const float* __restrict__ noise_gain,
    const float* __restrict__ bright_gain, float4* __restrict__ out)
{
    const unsigned gid = blockIdx.x * blockDim.x + threadIdx.x;   // 0 .. 1048575
    const unsigned b  = gid >> 16;        // / HW4
    const unsigned p  = gid & (HW4 - 1);

    const size_t ibase = (size_t)b * 3 * HW4 + p;
    const float4 r4 = img[ibase];
    const float4 g4 = img[ibase + HW4];
    const float4 b4 = img[ibase + 2 * HW4];
    const float4 n4 = noise[(size_t)b * HW4 + p];

    const float kd = density_k[0];
    const float ng = noise_gain[0];
    const float bg = bright_gain[0];

    float4 ro4, go4, bo4;
    {
        float3 o = pixel_op(r4.x, g4.x, b4.x, n4.x, kd, ng, bg);
        ro4.x = o.x; go4.x = o.y; bo4.x = o.z;
    }
    {
        float3 o = pixel_op(r4.y, g4.y, b4.y, n4.y, kd, ng, bg);
        ro4.y = o.x; go4.y = o.y; bo4.y = o.z;
    }
    {
        float3 o = pixel_op(r4.z, g4.z, b4.z, n4.z, kd, ng, bg);
        ro4.z = o.x; go4.z = o.y; bo4.z = o.z;
    }
    {
        float3 o = pixel_op(r4.w, g4.w, b4.w, n4.w, kd, ng, bg);
        ro4.w = o.x; go4.w = o.y; bo4.w = o.z;
    }

    out[ibase]           = ro4;
    out[ibase + HW4]     = go4;
    out[ibase + 2 * HW4] = bo4;
}

extern "C" void kernel_launch(void* const* d_in, const int* in_sizes, int n_in,
                              void* d_out, int out_size) {
    const float* img   = (const float*)d_in[0];
    const float* noise = (const float*)d_in[1];
    const float* kd    = (const float*)d_in[2];
    const float* ng    = (const float*)d_in[3];
    const float* bg    = (const float*)d_in[4];
    float* out = (float*)d_out;

    main_kernel<<<(NB * HW4) / 256, 256>>>(
        (const float4*)img, (const float4*)noise, kd, ng, bg, (float4*)out);
}

// round 4
// speedup vs baseline: 2.2191x; 1.0941x over previous
#include <cuda_runtime.h>

#define HW4      65536       // (512*512)/4
#define NB       16          // batch

#define EPSC 1e-8f
#define PIC  3.141592653589793f

// Fused per-pixel transform, fully branchless.
// Identities used (vs reference):
//  - sincos->atan2 round trip reconstructs hue exactly (hue_bias cancels);
//    s = sqrt((sat*cs/(cs+eps))^2 + eps).
//  - mod(x,6) for x in (-1,1) is x<0 ? x+6 : x.
//  - h*6 == h6 directly (skip /6*6 round trip; wheel is value-continuous at
//    integer boundaries so ulp-level floor flips are harmless).
//  - select-table == branchless wheel: chan(n) = vv - vv*s*sat01(min(k,4-k)),
//    k = wrap6(n + h6), n = 5/3/1 for r/g/b.  h6==6 edge -> black via mask.
__device__ __forceinline__ float3 pixel_op(float r, float g, float bch, float noi,
                                           float kd, float ng, float bg) {
    const float v  = fmaxf(r, fmaxf(g, bch));
    const float mn = fminf(r, fminf(g, bch));
    const float inv_denom = __fdividef(1.f, v - mn + EPSC);

    const bool rm = (r == v);
    const bool gm = (g == v);
    const float num = rm ? (g - bch) : (gm ? (bch - r) : (r - g));
    const float off = rm ? 0.f : (gm ? 2.f : 4.f);
    float h6 = fmaf(num, inv_denom, off);
    h6 = (h6 < 0.f) ? h6 + 6.f : h6;          // only reachable in rm case

    const float sat = __fdividef(v - mn, v + EPSC);   // v==0 -> 0 automatically

    const float kmap = fminf(fmaxf(fmaf(ng, noi, kd) - bg * v, 0.05f), 2.f);
    const float s1 = __sinf(v * (0.5f * PIC)) + EPSC;
    const float cs = __powf(s1, kmap);
    const float sr = sat * cs * __fdividef(1.f, cs + EPSC);

    const float x = fmaf(sr, sr, EPSC);
    const float s = fminf(x * rsqrtf(x), 1.f);        // sqrt(x), clip 1

    const float mask = (h6 < 6.f) ? 1.f : 0.f;        // hi==6 -> black
    const float vv = __saturatef(v) * mask;
    const float vs = vv * s;

    float3 o;
    {   // R: n = 5
        float k = 5.f + h6;  k = (k < 6.f) ? k : k - 6.f;
        float w = __saturatef(fminf(k, 4.f - k));
        o.x = fmaf(-vs, w, vv);
    }
    {   // G: n = 3
        float k = 3.f + h6;  k = (k < 6.f) ? k : k - 6.f;
        float w = __saturatef(fminf(k, 4.f - k));
        o.y = fmaf(-vs, w, vv);
    }
    {   // B: n = 1
        float k = 1.f + h6;  k = (k < 6.f) ? k : k - 6.f;
        float w = __saturatef(fminf(k, 4.f - k));
        o.z = fmaf(-vs, w, vv);
    }
    return o;
}

__global__ void __launch_bounds__(256) main_kernel(
    const float4* __restrict__ img, const float4* __restrict__ noise,
    const float* __restrict__ density_k, const float* __restrict__ noise_gain,
    const float* __restrict__ bright_gain, float4* __restrict__ out)
{
    const unsigned gid = blockIdx.x * blockDim.x + threadIdx.x;   // 0 .. 1048575
    const unsigned b  = gid >> 16;        // / HW4
    const unsigned p  = gid & (HW4 - 1);

    const size_t ibase = (size_t)b * 3 * HW4 + p;
    const float4 r4 = img[ibase];
    const float4 g4 = img[ibase + HW4];
    const float4 b4 = img[ibase + 2 * HW4];
    const float4 n4 = noise[(size_t)b * HW4 + p];

    const float kd = __ldg(density_k);
    const float ng = __ldg(noise_gain);
    const float bg = __ldg(bright_gain);

    float4 ro4, go4, bo4;
    {
        float3 o = pixel_op(r4.x, g4.x, b4.x, n4.x, kd, ng, bg);
        ro4.x = o.x; go4.x = o.y; bo4.x = o.z;
    }
    {
        float3 o = pixel_op(r4.y, g4.y, b4.y, n4.y, kd, ng, bg);
        ro4.y = o.x; go4.y = o.y; bo4.y = o.z;
    }
    {
        float3 o = pixel_op(r4.z, g4.z, b4.z, n4.z, kd, ng, bg);
        ro4.z = o.x; go4.z = o.y; bo4.z = o.z;
    }
    {
        float3 o = pixel_op(r4.w, g4.w, b4.w, n4.w, kd, ng, bg);
        ro4.w = o.x; go4.w = o.y; bo4.w = o.z;
    }

    out[ibase]           = ro4;
    out[ibase + HW4]     = go4;
    out[ibase + 2 * HW4] = bo4;
}

extern "C" void kernel_launch(void* const* d_in, const int* in_sizes, int n_in,
                              void* d_out, int out_size) {
    const float* img   = (const float*)d_in[0];
    const float* noise = (const float*)d_in[1];
    const float* kd    = (const float*)d_in[2];
    const float* ng    = (const float*)d_in[3];
    const float* bg    = (const float*)d_in[4];
    float* out = (float*)d_out;

    main_kernel<<<(NB * HW4) / 256, 256>>>(
        (const float4*)img, (const float4*)noise, kd, ng, bg, (float4*)out);
}